// round 13
// baseline (speedup 1.0000x reference)
#include <cuda_runtime.h>

// CreateOverlappingWindows: x (B=64, T=2000, C=26) fp32 ->
// out (B*T, 19*26), N_CONTEXT=9, zero-padded edges.
//
// Champion datapath (R11): direct gather, 2x LDG.64 -> STG.128 streaming
// (.cs), tile-local index math, interior/edge loop specialization.
// This round: exact 2.0-wave grid. 1184 blocks = 2 x 592 resident
// (4 x 512thr per SM x 148 SMs). 1184 = 32*19 + 32*18: first 32 batches
// get 19 blocks, rest get 18. Each batch's 2000 rows partitioned into
// even-sized even-count ranges r0 = 2*floor(j*1000/nb) (104-112 rows),
// keeping every block's output base 16B-aligned.
//
// src for flat offset fe within block: trow = fe/494,
// p = s0 + fe - trow*468, valid iff (unsigned)p < 52000 (edge blocks).

#define B_DIM   64
#define T_DIM   2000
#define C_DIM   26
#define NCTX    9
#define WINDOW  19
#define ROW_F   (WINDOW * C_DIM)          // 494
#define SLIDE   (ROW_F - C_DIM)           // 468
#define XROW_F  (T_DIM * C_DIM)           // 52000 floats per batch
#define NTHREADS 512
#define NBLOCKS  1184                      // exactly 2 waves of 592

__global__ __launch_bounds__(NTHREADS) void overlap_windows_kernel(
    const float* __restrict__ x, float* __restrict__ out)
{
    const int k = blockIdx.x;

    // map block -> (batch b, local block j of nb)
    int b, j, nb;
    if (k < 32 * 19) {
        b  = k / 19;
        j  = k - b * 19;
        nb = 19;
    } else {
        const int k2 = k - 32 * 19;
        const int bb = k2 / 18;
        b  = 32 + bb;
        j  = k2 - bb * 18;
        nb = 18;
    }

    // even-aligned row range [r0, r1) within batch b
    const int r0 = 2 * ((j * 1000) / nb);
    const int r1 = 2 * (((j + 1) * 1000) / nb);
    const int L4 = ((r1 - r0) / 2) * (ROW_F / 2);   // (r1-r0)*494/4 float4s

    const int tid = threadIdx.x;
    const float* xb = x + (size_t)b * XROW_F;
    float* tout = out + ((size_t)b * T_DIM + r0) * ROW_F;  // 16B aligned
    const int s0 = (r0 - NCTX) * C_DIM;   // negative only for j==0

    if (j != 0 && j != nb - 1) {
        // ---- interior blocks: no boundary checks ----
        #pragma unroll 4
        for (int i4 = tid; i4 < L4; i4 += NTHREADS) {
            const int fe = i4 * 4;

            const int trow0 = fe / ROW_F;                 // mul-hi divide
            const int k0    = fe - trow0 * ROW_F;         // 0..492, even
            const int p0    = s0 + fe - trow0 * SLIDE;
            const int trow1 = trow0 + ((k0 + 2 >= ROW_F) ? 1 : 0);
            const int p1    = s0 + (fe + 2) - trow1 * SLIDE;

            const float2 a = *reinterpret_cast<const float2*>(xb + p0);
            const float2 c = *reinterpret_cast<const float2*>(xb + p1);

            __stcs(reinterpret_cast<float4*>(tout + fe),
                   make_float4(a.x, a.y, c.x, c.y));
        }
    } else {
        // ---- edge blocks: predicated loads against [0, 52000) ----
        #pragma unroll 4
        for (int i4 = tid; i4 < L4; i4 += NTHREADS) {
            const int fe = i4 * 4;

            const int trow0 = fe / ROW_F;
            const int k0    = fe - trow0 * ROW_F;
            const int p0    = s0 + fe - trow0 * SLIDE;
            const int trow1 = trow0 + ((k0 + 2 >= ROW_F) ? 1 : 0);
            const int p1    = s0 + (fe + 2) - trow1 * SLIDE;

            float2 a = make_float2(0.0f, 0.0f);
            float2 c = make_float2(0.0f, 0.0f);
            if ((unsigned)p0 < (unsigned)XROW_F)
                a = *reinterpret_cast<const float2*>(xb + p0);
            if ((unsigned)p1 < (unsigned)XROW_F)
                c = *reinterpret_cast<const float2*>(xb + p1);

            __stcs(reinterpret_cast<float4*>(tout + fe),
                   make_float4(a.x, a.y, c.x, c.y));
        }
    }
}

extern "C" void kernel_launch(void* const* d_in, const int* in_sizes, int n_in,
                              void* d_out, int out_size)
{
    const float* x = (const float*)d_in[0];
    float* out = (float*)d_out;

    overlap_windows_kernel<<<NBLOCKS, NTHREADS>>>(x, out);
}

// round 14
// speedup vs baseline: 1.0421x; 1.0421x over previous
#include <cuda_runtime.h>

// CreateOverlappingWindows: x (B=64, T=2000, C=26) fp32 ->
// out (B*T, 19*26), N_CONTEXT=9, zero-padded edges.
//
// Champion datapath (R11): direct gather, 2x LDG.64 -> STG.128 streaming
// (.cs), tile-local index math, interior/edge loop specialization.
// This round: block-size sweep final step — 1024 threads, TILE_T=200
// (640 uniform blocks, 2 resident/SM, same 2.16-wave shape, half the
// block-dispatch overhead, ~24 store iterations per thread).
//
// src for flat tile offset fe: trow = fe/494, p = s0 + fe - trow*468,
// valid iff (unsigned)p < 52000 (edge tiles only).

#define B_DIM   64
#define T_DIM   2000
#define C_DIM   26
#define NCTX    9
#define WINDOW  19
#define ROW_F   (WINDOW * C_DIM)          // 494
#define SLIDE   (ROW_F - C_DIM)           // 468
#define XROW_F  (T_DIM * C_DIM)           // 52000 floats per batch
#define TILE_T  200                        // output rows per block (even)
#define NTILES  (T_DIM / TILE_T)           // 10
#define TILE_F4 (TILE_T * ROW_F / 4)       // 24700 float4 per tile
#define NTHREADS 1024

__global__ __launch_bounds__(NTHREADS) void overlap_windows_kernel(
    const float* __restrict__ x, float* __restrict__ out)
{
    const int tile = blockIdx.x;          // 0..9
    const int b    = blockIdx.y;          // 0..63
    const int t0   = tile * TILE_T;
    const int tid  = threadIdx.x;

    const float* xb = x + (size_t)b * XROW_F;
    float* tout = out + ((size_t)b * T_DIM + t0) * ROW_F;  // 16B aligned
    const int s0 = (t0 - NCTX) * C_DIM;   // negative only for tile 0

    if (tile != 0 && tile != NTILES - 1) {
        // ---- interior tiles (80% of work): no boundary checks ----
        #pragma unroll 4
        for (int i4 = tid; i4 < TILE_F4; i4 += NTHREADS) {
            const int fe = i4 * 4;

            const int trow0 = fe / ROW_F;                 // mul-hi divide
            const int k0    = fe - trow0 * ROW_F;         // 0..492, even
            const int p0    = s0 + fe - trow0 * SLIDE;
            const int trow1 = trow0 + ((k0 + 2 >= ROW_F) ? 1 : 0);
            const int p1    = s0 + (fe + 2) - trow1 * SLIDE;

            const float2 a = *reinterpret_cast<const float2*>(xb + p0);
            const float2 c = *reinterpret_cast<const float2*>(xb + p1);

            __stcs(reinterpret_cast<float4*>(tout + fe),
                   make_float4(a.x, a.y, c.x, c.y));
        }
    } else {
        // ---- edge tiles: predicated loads against [0, 52000) ----
        #pragma unroll 4
        for (int i4 = tid; i4 < TILE_F4; i4 += NTHREADS) {
            const int fe = i4 * 4;

            const int trow0 = fe / ROW_F;
            const int k0    = fe - trow0 * ROW_F;
            const int p0    = s0 + fe - trow0 * SLIDE;
            const int trow1 = trow0 + ((k0 + 2 >= ROW_F) ? 1 : 0);
            const int p1    = s0 + (fe + 2) - trow1 * SLIDE;

            float2 a = make_float2(0.0f, 0.0f);
            float2 c = make_float2(0.0f, 0.0f);
            if ((unsigned)p0 < (unsigned)XROW_F)
                a = *reinterpret_cast<const float2*>(xb + p0);
            if ((unsigned)p1 < (unsigned)XROW_F)
                c = *reinterpret_cast<const float2*>(xb + p1);

            __stcs(reinterpret_cast<float4*>(tout + fe),
                   make_float4(a.x, a.y, c.x, c.y));
        }
    }
}

extern "C" void kernel_launch(void* const* d_in, const int* in_sizes, int n_in,
                              void* d_out, int out_size)
{
    const float* x = (const float*)d_in[0];
    float* out = (float*)d_out;

    dim3 grid(NTILES, B_DIM);             // 10 x 64 = 640 blocks
    overlap_windows_kernel<<<grid, NTHREADS>>>(x, out);
}

// round 15
// speedup vs baseline: 1.0990x; 1.0546x over previous
#include <cuda_runtime.h>

// CreateOverlappingWindows: x (B=64, T=2000, C=26) fp32 ->
// out (B*T, 19*26), N_CONTEXT=9, zero-padded edges.
//
// FINAL (champion, measured 41.0 us ~ 6.5 TB/s effective, HBM write
// roofline). out row (b,t) = contiguous x slice x[b, t-9 : t+10, :]
// flattened. Direct gather: 2x LDG.64 (L2/L1-resident source) ->
// 1x STG.128 streaming (.cs), flat fully-coalesced stores.
// TILE_T=100 rows/block, 512 threads, 1280 blocks (4 blocks/SM).
// Edge specialization: only tiles 0 and 19 carry zero-padding range
// checks; 18/20 interior tiles run an unpredicated loop.
//
// Sweep results (all passed, wall us): smem-staged 47.6/43.7; direct-f2
// 44.3; direct-f4+.cs 43.5; STG.256 49.9; no-.cs 49.8; TMA bulk 49.2;
// grid-swap 45.1; persistent 43.1; TILE100/512thr 41.2; +edge-spec 41.0;
// 2.0-wave 45.1; 1024thr 43.3.  => this config is the optimum.
//
// src for flat tile offset fe: trow = fe/494, p = s0 + fe - trow*468,
// valid iff (unsigned)p < 52000 (edge tiles only).

#define B_DIM   64
#define T_DIM   2000
#define C_DIM   26
#define NCTX    9
#define WINDOW  19
#define ROW_F   (WINDOW * C_DIM)          // 494
#define SLIDE   (ROW_F - C_DIM)           // 468
#define XROW_F  (T_DIM * C_DIM)           // 52000 floats per batch
#define TILE_T  100                        // output rows per block
#define NTILES  (T_DIM / TILE_T)           // 20
#define TILE_F4 (TILE_T * ROW_F / 4)       // 12350 float4 per tile
#define NTHREADS 512

__global__ __launch_bounds__(NTHREADS) void overlap_windows_kernel(
    const float* __restrict__ x, float* __restrict__ out)
{
    const int tile = blockIdx.x;          // 0..19
    const int b    = blockIdx.y;          // 0..63
    const int t0   = tile * TILE_T;
    const int tid  = threadIdx.x;

    const float* xb = x + (size_t)b * XROW_F;
    float* tout = out + ((size_t)b * T_DIM + t0) * ROW_F;  // 16B aligned
    const int s0 = (t0 - NCTX) * C_DIM;   // negative only for tile 0

    if (tile != 0 && tile != NTILES - 1) {
        // ---- interior tiles (90% of work): no boundary checks ----
        #pragma unroll 4
        for (int i4 = tid; i4 < TILE_F4; i4 += NTHREADS) {
            const int fe = i4 * 4;

            const int trow0 = fe / ROW_F;                 // mul-hi divide
            const int k0    = fe - trow0 * ROW_F;         // 0..492, even
            const int p0    = s0 + fe - trow0 * SLIDE;
            const int trow1 = trow0 + ((k0 + 2 >= ROW_F) ? 1 : 0);
            const int p1    = s0 + (fe + 2) - trow1 * SLIDE;

            const float2 a = *reinterpret_cast<const float2*>(xb + p0);
            const float2 c = *reinterpret_cast<const float2*>(xb + p1);

            __stcs(reinterpret_cast<float4*>(tout + fe),
                   make_float4(a.x, a.y, c.x, c.y));
        }
    } else {
        // ---- edge tiles: predicated loads against [0, 52000) ----
        #pragma unroll 4
        for (int i4 = tid; i4 < TILE_F4; i4 += NTHREADS) {
            const int fe = i4 * 4;

            const int trow0 = fe / ROW_F;
            const int k0    = fe - trow0 * ROW_F;
            const int p0    = s0 + fe - trow0 * SLIDE;
            const int trow1 = trow0 + ((k0 + 2 >= ROW_F) ? 1 : 0);
            const int p1    = s0 + (fe + 2) - trow1 * SLIDE;

            float2 a = make_float2(0.0f, 0.0f);
            float2 c = make_float2(0.0f, 0.0f);
            if ((unsigned)p0 < (unsigned)XROW_F)
                a = *reinterpret_cast<const float2*>(xb + p0);
            if ((unsigned)p1 < (unsigned)XROW_F)
                c = *reinterpret_cast<const float2*>(xb + p1);

            __stcs(reinterpret_cast<float4*>(tout + fe),
                   make_float4(a.x, a.y, c.x, c.y));
        }
    }
}

extern "C" void kernel_launch(void* const* d_in, const int* in_sizes, int n_in,
                              void* d_out, int out_size)
{
    const float* x = (const float*)d_in[0];
    float* out = (float*)d_out;

    dim3 grid(NTILES, B_DIM);             // 20 x 64 = 1280 blocks
    overlap_windows_kernel<<<grid, NTHREADS>>>(x, out);
}